// round 15
// baseline (speedup 1.0000x reference)
#include <cuda_runtime.h>
#include <cuda_fp16.h>
#include <math.h>
#include <stdint.h>

// ---------------- problem constants ----------------
#define TT   8192              // tokens (B*S)
#define DD   2048              // model dim
#define HH   1368              // hidden dim
#define HP   1408              // hidden padded to 64
#define EE   8                 // experts
#define TK   16384             // T * K routed assignments
#define TKS  24576             // TK + TT (shared expert appended as segment 8)
#define WMAT (HH * DD)         // elements per weight matrix

// ---------------- static device scratch ----------------
__device__ __align__(16) __half g_xh[(size_t)TT * DD];      // x (fp16, token order)
__device__ __align__(16) __half g_hh[(size_t)TKS * HP];     // swiglu output (fp16)
__device__ __align__(16) __half g_bufAh[(size_t)TKS * HP];  // x@w1^T (fp16)
__device__ __align__(16) __half g_bufBh[(size_t)TKS * HP];  // x@w3^T (fp16)
__device__ __align__(16) float  g_y[(size_t)TKS * DD];      // gemm2 output slots
__device__ __align__(16) __half g_w1h[(size_t)9 * WMAT];
__device__ __align__(16) __half g_w3h[(size_t)9 * WMAT];
__device__ __align__(16) __half g_w2h[(size_t)9 * WMAT];
__device__ int    g_tok[TKS];
__device__ float  g_gatev[TKS];
__device__ int    g_pos[2 * TT];
__device__ int2   g_top_e[TT];
__device__ float2 g_top_p[TT];
__device__ int    g_cnt1[EE];
__device__ int    g_cntA[EE];
__device__ int    g_cur[EE];
__device__ int    g_seg[10];
__device__ float  g_psum[EE];

// ---------------- PTX helpers (baseline-arch safe) ----------------
__device__ __forceinline__ unsigned smem_u32(const void* p) {
    unsigned a;
    asm("{ .reg .u64 t; cvta.to.shared.u64 t, %1; cvt.u32.u64 %0, t; }"
        : "=r"(a) : "l"(p));
    return a;
}
#define CP_COMMIT()  asm volatile("cp.async.commit_group;" ::: "memory")
#define CP_WAIT0()   asm volatile("cp.async.wait_group 0;" ::: "memory")
#define CP_WAIT1()   asm volatile("cp.async.wait_group 1;" ::: "memory")
#define CP16(dst, src, sz) \
    asm volatile("cp.async.cg.shared.global [%0], [%1], 16, %2;" \
                 :: "r"(dst), "l"(src), "r"(sz))

#define LDSM4(r, addr) \
    asm volatile("ldmatrix.sync.aligned.m8n8.x4.shared.b16 {%0,%1,%2,%3}, [%4];" \
        : "=r"((r)[0]), "=r"((r)[1]), "=r"((r)[2]), "=r"((r)[3]) : "r"(addr))

#define MMAF16(c, a, b0, b1) \
    asm volatile("mma.sync.aligned.m16n8k16.row.col.f32.f16.f16.f32 " \
        "{%0,%1,%2,%3}, {%4,%5,%6,%7}, {%8,%9}, {%0,%1,%2,%3};" \
        : "+f"((c)[0]), "+f"((c)[1]), "+f"((c)[2]), "+f"((c)[3]) \
        : "r"((a)[0]), "r"((a)[1]), "r"((a)[2]), "r"((a)[3]), "r"(b0), "r"(b1))

// ---------------- routing ----------------
__global__ void init_kernel() {
    int i = threadIdx.x;
    if (i < EE) { g_cnt1[i] = 0; g_cntA[i] = 0; g_psum[i] = 0.f; g_cur[i] = 0; }
}

__global__ void router_kernel(const float* __restrict__ x,
                              const float* __restrict__ rw) {
    __shared__ float s_psum[EE];
    __shared__ int s_cnt1[EE], s_cntA[EE];
    int tid = threadIdx.x;
    if (tid < EE) { s_psum[tid] = 0.f; s_cnt1[tid] = 0; s_cntA[tid] = 0; }
    __syncthreads();

    int warp = tid >> 5, lane = tid & 31;
    int t = blockIdx.x * 8 + warp;

    float acc[EE];
#pragma unroll
    for (int e = 0; e < EE; e++) acc[e] = 0.f;
    const float4* xr = reinterpret_cast<const float4*>(x + (long long)t * DD);
    for (int d4 = lane; d4 < DD / 4; d4 += 32) {
        float4 xv = xr[d4];
#pragma unroll
        for (int e = 0; e < EE; e++) {
            float4 wv = reinterpret_cast<const float4*>(rw + (long long)e * DD)[d4];
            acc[e] += xv.x * wv.x + xv.y * wv.y + xv.z * wv.z + xv.w * wv.w;
        }
    }
#pragma unroll
    for (int e = 0; e < EE; e++)
        for (int o = 16; o; o >>= 1)
            acc[e] += __shfl_xor_sync(0xffffffffu, acc[e], o);

    if (lane == 0) {
        float mx = acc[0];
#pragma unroll
        for (int e = 1; e < EE; e++) mx = fmaxf(mx, acc[e]);
        float p[EE], s = 0.f;
#pragma unroll
        for (int e = 0; e < EE; e++) { p[e] = expf(acc[e] - mx); s += p[e]; }
        float inv = 1.f / s;
        int e0 = 0;
#pragma unroll
        for (int e = 1; e < EE; e++) if (acc[e] > acc[e0]) e0 = e;
        int e1 = (e0 == 0) ? 1 : 0;
#pragma unroll
        for (int e = 0; e < EE; e++) if (e != e0 && acc[e] > acc[e1]) e1 = e;

        g_top_e[t] = make_int2(e0, e1);
        g_top_p[t] = make_float2(p[e0] * inv, p[e1] * inv);
        atomicAdd(&s_cnt1[e0], 1);
        atomicAdd(&s_cntA[e0], 1);
        atomicAdd(&s_cntA[e1], 1);
#pragma unroll
        for (int e = 0; e < EE; e++) atomicAdd(&s_psum[e], p[e] * inv);
    }
    __syncthreads();
    if (tid < EE) {
        atomicAdd(&g_psum[tid], s_psum[tid]);
        atomicAdd(&g_cnt1[tid], s_cnt1[tid]);
        atomicAdd(&g_cntA[tid], s_cntA[tid]);
    }
}

__global__ void scan_kernel(float* __restrict__ aux_out) {
    if (threadIdx.x == 0) {
        int off = 0;
        for (int e = 0; e < EE; e++) { g_seg[e] = off; off += g_cntA[e]; }
        g_seg[8] = TK;
        g_seg[9] = TKS;
        float aux = 0.f;
        const float invT = 1.0f / (float)TT;
        for (int e = 0; e < EE; e++)
            aux += ((float)g_cnt1[e] * invT) * (g_psum[e] * invT);
        aux_out[0] = 0.01f * (float)EE * aux;
    }
}

__global__ void build_kernel() {
    int t = blockIdx.x * blockDim.x + threadIdx.x;
    if (t >= TT) return;
    int2 e = g_top_e[t];
    float2 p = g_top_p[t];
    int pos0 = g_seg[e.x] + atomicAdd(&g_cur[e.x], 1);
    g_tok[pos0] = t; g_gatev[pos0] = p.x; g_pos[2 * t] = pos0;
    int pos1 = g_seg[e.y] + atomicAdd(&g_cur[e.y], 1);
    g_tok[pos1] = t; g_gatev[pos1] = p.y; g_pos[2 * t + 1] = pos1;
    g_tok[TK + t] = t; g_gatev[TK + t] = 1.0f;
}

// ---------------- fp16 convert x (token order, L2-resident) ----------------
__global__ void conv_x(const float* __restrict__ x) {
    int i = blockIdx.x * blockDim.x + threadIdx.x;
    if (i >= TT * (DD / 4)) return;
    float4 v = reinterpret_cast<const float4*>(x)[i];
    long long o = (long long)i * 2;
    reinterpret_cast<__half2*>(g_xh)[o]     = __floats2half2_rn(v.x, v.y);
    reinterpret_cast<__half2*>(g_xh)[o + 1] = __floats2half2_rn(v.z, v.w);
}

// ---------------- fp16 convert all 6 weight tensors (one launch) ----------
__global__ void conv_w_all(const float* __restrict__ w1, const float* __restrict__ sw1,
                           const float* __restrict__ w3, const float* __restrict__ sw3,
                           const float* __restrict__ w2, const float* __restrict__ sw2) {
    int job = blockIdx.y;                   // 0..5
    const float* src;
    __half* dst;
    int n4;
    const int nw = 8 * WMAT / 4, ns = WMAT / 4;
    switch (job) {
        case 0:  src = w1;  dst = g_w1h;                    n4 = nw; break;
        case 1:  src = sw1; dst = g_w1h + (size_t)8 * WMAT; n4 = ns; break;
        case 2:  src = w3;  dst = g_w3h;                    n4 = nw; break;
        case 3:  src = sw3; dst = g_w3h + (size_t)8 * WMAT; n4 = ns; break;
        case 4:  src = w2;  dst = g_w2h;                    n4 = nw; break;
        default: src = sw2; dst = g_w2h + (size_t)8 * WMAT; n4 = ns; break;
    }
    for (int i = blockIdx.x * blockDim.x + threadIdx.x; i < n4;
         i += gridDim.x * blockDim.x) {
        float4 v = reinterpret_cast<const float4*>(src)[i];
        long long o = (long long)i * 2;
        reinterpret_cast<__half2*>(dst)[o]     = __floats2half2_rn(v.x, v.y);
        reinterpret_cast<__half2*>(dst)[o + 1] = __floats2half2_rn(v.z, v.w);
    }
}

// ---------------- swiglu (fp16 in, fp16 out) ----------------
__global__ void swiglu_half(int n4) {
    int i = blockIdx.x * blockDim.x + threadIdx.x;
    if (i >= n4) return;
    const __half2* a2 = reinterpret_cast<const __half2*>(g_bufAh);
    const __half2* b2 = reinterpret_cast<const __half2*>(g_bufBh);
    long long o = (long long)i * 2;
    __half2 a0 = a2[o], a1 = a2[o + 1];
    __half2 b0 = b2[o], b1 = b2[o + 1];
    float ax = __low2float(a0), ay = __high2float(a0);
    float az = __low2float(a1), aw = __high2float(a1);
    float bx = __low2float(b0), by = __high2float(b0);
    float bz = __low2float(b1), bw = __high2float(b1);
    float hx = ax / (1.f + __expf(-ax)) * bx;
    float hy = ay / (1.f + __expf(-ay)) * by;
    float hz = az / (1.f + __expf(-az)) * bz;
    float hw = aw / (1.f + __expf(-aw)) * bw;
    reinterpret_cast<__half2*>(g_hh)[o]     = __floats2half2_rn(hx, hy);
    reinterpret_cast<__half2*>(g_hh)[o + 1] = __floats2half2_rn(hz, hw);
}

// ============================================================================
// grouped FP16 GEMM via mma.sync m16n8k16 (fp32 accumulate)
// 256x128 CTA tile (512 threads, 16 warps as 8m x 2n; each warp m32 x n64),
// K64 chunks, 3-stage pipeline, ONE sync per chunk.
// gate == null -> fp16 output; gate != null -> gated fp32 output.
// Optional per-tile row gather for A. W3 selects merged-GEMM1 second half.
// ============================================================================
#define MPITCH 144                          // 128B K64 data + 16B stagger
#define ATILE  (256 * MPITCH)               // 36864 bytes (A: 256 rows)
#define BTILE  (128 * MPITCH)               // 18432 bytes (B: 128 rows)
#define HSTAGE (ATILE + BTILE)              // 55296
#define HSMEM  (3 * HSTAGE)                 // 165888 bytes total

__device__ __forceinline__ void ld_tiles_h(
    unsigned tb, int tid,
    const __half* __restrict__ A, const __half* __restrict__ B,
    const int* __restrict__ stok,           // smem token map or null
    int row0, int lda, int col0, int ldb, int nreal, int kreal, int kc0)
{
#pragma unroll
    for (int j = 0; j < 6; j++) {
        int idx = j * 512 + tid;         // 0..3071
        if (idx < 2048) {                // A: 256 rows x 8 chunks
            int r = idx >> 3, c = idx & 7;
            unsigned off = (unsigned)(r * MPITCH + c * 16);
            int ar;
            if (stok) ar = stok[r];
            else { ar = row0 + r; if (ar >= TKS) ar = TKS - 1; }
            long long ga = (long long)ar * lda + kc0 + c * 8;
            CP16(tb + off, A + ga, 16);
        } else {                         // B: 128 rows x 8 chunks
            int li = idx - 2048;
            int r = li >> 3, c = li & 7;
            unsigned off = (unsigned)(r * MPITCH + c * 16);
            int n = col0 + r, kg = kc0 + c * 8;
            int ok = (n < nreal && kg < kreal) ? 16 : 0;
            long long gb = ok ? ((long long)n * ldb + kg) : 0;
            CP16(tb + ATILE + off, B + gb, ok);
        }
    }
    CP_COMMIT();
}

__global__ __launch_bounds__(512, 1)
void gemm_h(const __half* __restrict__ A,
            const __half* __restrict__ W1, const __half* __restrict__ W3,
            void* __restrict__ C1, void* __restrict__ C3,
            const float* __restrict__ gate,
            const int* __restrict__ gather,
            int lda, int ldb, int ldc, int nreal, int kreal, int kpad, int nx)
{
    extern __shared__ __align__(128) char smem[];
    __shared__ int s_tok[256];

    int z  = blockIdx.z;
    int m0 = g_seg[z], m1 = g_seg[z + 1];
    int row0 = m0 + blockIdx.y * 256;
    if (row0 >= m1) return;

    const __half* W = W1;
    void* C = C1;
    int cx = blockIdx.x;
    if (W3 != nullptr && cx >= nx) { W = W3; C = C3; cx -= nx; }
    int col0 = cx * 128;
    const __half* B = W + (long long)z * WMAT;

    unsigned sb = smem_u32(smem);
    int tid = threadIdx.x, wid = tid >> 5, lane = tid & 31;
    int nch = kpad / 64;
    int wm = wid & 7, wn = wid >> 3;          // warp -> (m32 of 256, n64 of 128)

    // stage token map for gathered A rows
    if (gather != nullptr) {
        if (tid < 256) {
            int rr = row0 + tid;
            s_tok[tid] = gather[(rr < m1) ? rr : m0];
        }
        __syncthreads();
    }
    const int* stok = (gather != nullptr) ? s_tok : nullptr;

    float acc[2][8][4];
#pragma unroll
    for (int t = 0; t < 2; t++)
#pragma unroll
        for (int n = 0; n < 8; n++)
#pragma unroll
            for (int q = 0; q < 4; q++) acc[t][n][q] = 0.f;

    // ldmatrix lane offsets (f16 family; k-step byte advance added in loop)
    unsigned a_off[2], b_off[4];
#pragma unroll
    for (int t = 0; t < 2; t++) {
        int rr = wm * 32 + t * 16 + ((lane >> 3) & 1) * 8 + (lane & 7);
        a_off[t] = (unsigned)(rr * MPITCH + (lane >> 4) * 16);
    }
#pragma unroll
    for (int p = 0; p < 4; p++) {
        int nn = wn * 64 + p * 16 + (lane >> 4) * 8 + (lane & 7);
        b_off[p] = (unsigned)(ATILE + nn * MPITCH + ((lane >> 3) & 1) * 16);
    }

    // prologue: stages 0, 1 <- chunks 0, 1
    ld_tiles_h(sb,          tid, A, B, stok, row0, lda, col0, ldb, nreal, kreal, 0);
    ld_tiles_h(sb + HSTAGE, tid, A, B, stok, row0, lda, col0, ldb, nreal, kreal, 64);

    for (int i = 0; i < nch; i++) {
        if (i + 1 < nch) CP_WAIT1(); else CP_WAIT0();
        __syncthreads();
        if (i + 2 < nch) {
            ld_tiles_h(sb + ((i + 2) % 3) * HSTAGE, tid, A, B, stok,
                       row0, lda, col0, ldb, nreal, kreal, (i + 2) * 64);
        }

        unsigned tb = sb + (i % 3) * HSTAGE;
#pragma unroll
        for (int ks = 0; ks < 4; ks++) {
            unsigned kof = ks * 32;          // 16 halves = 32 bytes per k16 step
            unsigned av[2][4], bv[4][4];
            LDSM4(av[0], tb + a_off[0] + kof);
            LDSM4(av[1], tb + a_off[1] + kof);
#pragma unroll
            for (int p = 0; p < 4; p++)
                LDSM4(bv[p], tb + b_off[p] + kof);
#pragma unroll
            for (int p = 0; p < 4; p++)
#pragma unroll
                for (int t = 0; t < 2; t++) {
                    MMAF16(acc[t][2 * p],     av[t], bv[p][0], bv[p][1]);
                    MMAF16(acc[t][2 * p + 1], av[t], bv[p][2], bv[p][3]);
                }
        }
    }

    // epilogue
#pragma unroll
    for (int t = 0; t < 2; t++) {
        int r0 = row0 + wm * 32 + t * 16 + (lane >> 2);
        int r1 = r0 + 8;
        bool a0 = (r0 < m1), a1 = (r1 < m1);
        if (gate != nullptr) {
            float g0 = a0 ? gate[r0] : 1.f;
            float g1 = a1 ? gate[r1] : 1.f;
            float* Cf = (float*)C;
#pragma unroll
            for (int n = 0; n < 8; n++) {
                int cb = col0 + wn * 64 + n * 8 + 2 * (lane & 3);
                if (a0) {
                    float2 v = make_float2(acc[t][n][0] * g0, acc[t][n][1] * g0);
                    *reinterpret_cast<float2*>(Cf + (long long)r0 * ldc + cb) = v;
                }
                if (a1) {
                    float2 v = make_float2(acc[t][n][2] * g1, acc[t][n][3] * g1);
                    *reinterpret_cast<float2*>(Cf + (long long)r1 * ldc + cb) = v;
                }
            }
        } else {
            __half* Ch = (__half*)C;
#pragma unroll
            for (int n = 0; n < 8; n++) {
                int cb = col0 + wn * 64 + n * 8 + 2 * (lane & 3);
                if (a0) {
                    *reinterpret_cast<__half2*>(Ch + (long long)r0 * ldc + cb) =
                        __floats2half2_rn(acc[t][n][0], acc[t][n][1]);
                }
                if (a1) {
                    *reinterpret_cast<__half2*>(Ch + (long long)r1 * ldc + cb) =
                        __floats2half2_rn(acc[t][n][2], acc[t][n][3]);
                }
            }
        }
    }
}

// ---------------- final deterministic 3-slot add ----------------
__global__ void final_add(float* __restrict__ out) {
    int i = blockIdx.x * blockDim.x + threadIdx.x;
    if (i >= TT * (DD / 4)) return;
    int t = i >> 9, c = i & 511;
    int p0 = g_pos[2 * t], p1 = g_pos[2 * t + 1], p2 = TK + t;
    const float4* y4 = reinterpret_cast<const float4*>(g_y);
    float4 a = y4[(long long)p0 * 512 + c];
    float4 b = y4[(long long)p1 * 512 + c];
    float4 d = y4[(long long)p2 * 512 + c];
    float4 v;
    v.x = a.x + b.x + d.x; v.y = a.y + b.y + d.y;
    v.z = a.z + b.z + d.z; v.w = a.w + b.w + d.w;
    reinterpret_cast<float4*>(out)[(long long)t * 512 + c] = v;
}

// ---------------- launch ----------------
extern "C" void kernel_launch(void* const* d_in, const int* in_sizes, int n_in,
                              void* d_out, int out_size) {
    const float* x   = (const float*)d_in[0];
    const float* rw  = (const float*)d_in[1];
    const float* w1  = (const float*)d_in[2];
    const float* w2  = (const float*)d_in[3];
    const float* w3  = (const float*)d_in[4];
    const float* sw1 = (const float*)d_in[5];
    const float* sw2 = (const float*)d_in[6];
    const float* sw3 = (const float*)d_in[7];
    float* out = (float*)d_out;

    float *pY, *pGate;
    __half *pXh, *pHh, *pBufAh, *pBufBh, *pW1h, *pW3h, *pW2h;
    int *pTok;
    cudaGetSymbolAddress((void**)&pY,     g_y);
    cudaGetSymbolAddress((void**)&pGate,  g_gatev);
    cudaGetSymbolAddress((void**)&pXh,    g_xh);
    cudaGetSymbolAddress((void**)&pHh,    g_hh);
    cudaGetSymbolAddress((void**)&pBufAh, g_bufAh);
    cudaGetSymbolAddress((void**)&pBufBh, g_bufBh);
    cudaGetSymbolAddress((void**)&pW1h,   g_w1h);
    cudaGetSymbolAddress((void**)&pW3h,   g_w3h);
    cudaGetSymbolAddress((void**)&pW2h,   g_w2h);
    cudaGetSymbolAddress((void**)&pTok,   g_tok);

    cudaFuncSetAttribute(gemm_h, cudaFuncAttributeMaxDynamicSharedMemorySize, HSMEM);

    // routing
    init_kernel<<<1, 32>>>();
    router_kernel<<<TT / 8, 256>>>(x, rw);
    scan_kernel<<<1, 32>>>(out + (long long)TT * DD);
    build_kernel<<<TT / 256, 256>>>();

    // converts (x token order; all 6 weight tensors in one launch)
    conv_x<<<(TT * (DD / 4) + 255) / 256, 256>>>(x);
    {
        dim3 gw(1184, 6);
        conv_w_all<<<gw, 256>>>(w1, sw1, w3, sw3, w2, sw2);
    }

    // GEMM1 merged + in-GEMM gather: x<11 -> w1 -> bufA; >=11 -> w3 -> bufB
    dim3 grid1(22, 32, 9);
    gemm_h<<<grid1, 512, HSMEM>>>(pXh, pW1h, pW3h, pBufAh, pBufBh, nullptr, pTok,
                                  DD, DD, HP, HH, DD, 2048, 11);

    // swiglu (fp16 -> fp16)
    {
        int n4 = TKS * HP / 4;
        swiglu_half<<<(n4 + 255) / 256, 256>>>(n4);
    }

    // GEMM2: [TKS, HP] @ [DD, HH]^T -> y (gated fp32); kpad 1408
    dim3 grid2(16, 32, 9);
    gemm_h<<<grid2, 512, HSMEM>>>(pHh, pW2h, nullptr, pY, nullptr, pGate, nullptr,
                                  HP, HH, DD, DD, HH, 1408, 16);

    final_add<<<(TT * (DD / 4)) / 256, 256>>>(out);
}

// round 16
// speedup vs baseline: 1.1072x; 1.1072x over previous
#include <cuda_runtime.h>
#include <cuda_fp16.h>
#include <math.h>
#include <stdint.h>

// ---------------- problem constants ----------------
#define TT   8192              // tokens (B*S)
#define DD   2048              // model dim
#define HH   1368              // hidden dim
#define HP   1408              // hidden padded to 64
#define EE   8                 // experts
#define TK   16384             // T * K routed assignments
#define TKS  24576             // TK + TT (shared expert appended as segment 8)
#define WMAT (HH * DD)         // elements per weight matrix
#define NPERS 296              // persistent CTAs (148 SMs x 2)

// ---------------- static device scratch ----------------
__device__ __align__(16) __half g_xh[(size_t)TT * DD];      // x (fp16, token order)
__device__ __align__(16) __half g_hh[(size_t)TKS * HP];     // swiglu output (fp16)
__device__ __align__(16) __half g_bufAh[(size_t)TKS * HP];  // x@w1^T (fp16)
__device__ __align__(16) __half g_bufBh[(size_t)TKS * HP];  // x@w3^T (fp16)
__device__ __align__(16) float  g_y[(size_t)TKS * DD];      // gemm2 output slots
__device__ __align__(16) __half g_w1h[(size_t)9 * WMAT];
__device__ __align__(16) __half g_w3h[(size_t)9 * WMAT];
__device__ __align__(16) __half g_w2h[(size_t)9 * WMAT];
__device__ int    g_tok[TKS];
__device__ float  g_gatev[TKS];
__device__ int    g_pos[2 * TT];
__device__ int2   g_top_e[TT];
__device__ float2 g_top_p[TT];
__device__ int    g_cnt1[EE];
__device__ int    g_cntA[EE];
__device__ int    g_cur[EE];
__device__ int    g_seg[10];
__device__ float  g_psum[EE];
__device__ int    g_ytz[640];    // global y-tile -> (z << 16) | local y
__device__ int    g_nyt;         // number of real y-tiles
__device__ int    g_work1;       // work counter, GEMM1
__device__ int    g_work2;       // work counter, GEMM2

// ---------------- PTX helpers (baseline-arch safe) ----------------
__device__ __forceinline__ unsigned smem_u32(const void* p) {
    unsigned a;
    asm("{ .reg .u64 t; cvta.to.shared.u64 t, %1; cvt.u32.u64 %0, t; }"
        : "=r"(a) : "l"(p));
    return a;
}
#define CP_COMMIT()  asm volatile("cp.async.commit_group;" ::: "memory")
#define CP_WAIT0()   asm volatile("cp.async.wait_group 0;" ::: "memory")
#define CP_WAIT1()   asm volatile("cp.async.wait_group 1;" ::: "memory")
#define CP16(dst, src, sz) \
    asm volatile("cp.async.cg.shared.global [%0], [%1], 16, %2;" \
                 :: "r"(dst), "l"(src), "r"(sz))

#define LDSM4(r, addr) \
    asm volatile("ldmatrix.sync.aligned.m8n8.x4.shared.b16 {%0,%1,%2,%3}, [%4];" \
        : "=r"((r)[0]), "=r"((r)[1]), "=r"((r)[2]), "=r"((r)[3]) : "r"(addr))

#define MMAF16(c, a, b0, b1) \
    asm volatile("mma.sync.aligned.m16n8k16.row.col.f32.f16.f16.f32 " \
        "{%0,%1,%2,%3}, {%4,%5,%6,%7}, {%8,%9}, {%0,%1,%2,%3};" \
        : "+f"((c)[0]), "+f"((c)[1]), "+f"((c)[2]), "+f"((c)[3]) \
        : "r"((a)[0]), "r"((a)[1]), "r"((a)[2]), "r"((a)[3]), "r"(b0), "r"(b1))

// ---------------- routing ----------------
__global__ void init_kernel() {
    int i = threadIdx.x;
    if (i < EE) { g_cnt1[i] = 0; g_cntA[i] = 0; g_psum[i] = 0.f; g_cur[i] = 0; }
    if (i == 0) { g_work1 = 0; g_work2 = 0; }
}

__global__ void router_kernel(const float* __restrict__ x,
                              const float* __restrict__ rw) {
    __shared__ float s_psum[EE];
    __shared__ int s_cnt1[EE], s_cntA[EE];
    int tid = threadIdx.x;
    if (tid < EE) { s_psum[tid] = 0.f; s_cnt1[tid] = 0; s_cntA[tid] = 0; }
    __syncthreads();

    int warp = tid >> 5, lane = tid & 31;
    int t = blockIdx.x * 8 + warp;

    float acc[EE];
#pragma unroll
    for (int e = 0; e < EE; e++) acc[e] = 0.f;
    const float4* xr = reinterpret_cast<const float4*>(x + (long long)t * DD);
    for (int d4 = lane; d4 < DD / 4; d4 += 32) {
        float4 xv = xr[d4];
#pragma unroll
        for (int e = 0; e < EE; e++) {
            float4 wv = reinterpret_cast<const float4*>(rw + (long long)e * DD)[d4];
            acc[e] += xv.x * wv.x + xv.y * wv.y + xv.z * wv.z + xv.w * wv.w;
        }
    }
#pragma unroll
    for (int e = 0; e < EE; e++)
        for (int o = 16; o; o >>= 1)
            acc[e] += __shfl_xor_sync(0xffffffffu, acc[e], o);

    if (lane == 0) {
        float mx = acc[0];
#pragma unroll
        for (int e = 1; e < EE; e++) mx = fmaxf(mx, acc[e]);
        float p[EE], s = 0.f;
#pragma unroll
        for (int e = 0; e < EE; e++) { p[e] = expf(acc[e] - mx); s += p[e]; }
        float inv = 1.f / s;
        int e0 = 0;
#pragma unroll
        for (int e = 1; e < EE; e++) if (acc[e] > acc[e0]) e0 = e;
        int e1 = (e0 == 0) ? 1 : 0;
#pragma unroll
        for (int e = 0; e < EE; e++) if (e != e0 && acc[e] > acc[e1]) e1 = e;

        g_top_e[t] = make_int2(e0, e1);
        g_top_p[t] = make_float2(p[e0] * inv, p[e1] * inv);
        atomicAdd(&s_cnt1[e0], 1);
        atomicAdd(&s_cntA[e0], 1);
        atomicAdd(&s_cntA[e1], 1);
#pragma unroll
        for (int e = 0; e < EE; e++) atomicAdd(&s_psum[e], p[e] * inv);
    }
    __syncthreads();
    if (tid < EE) {
        atomicAdd(&g_psum[tid], s_psum[tid]);
        atomicAdd(&g_cnt1[tid], s_cnt1[tid]);
        atomicAdd(&g_cntA[tid], s_cntA[tid]);
    }
}

__global__ void scan_kernel(float* __restrict__ aux_out) {
    if (threadIdx.x == 0) {
        int off = 0;
        for (int e = 0; e < EE; e++) { g_seg[e] = off; off += g_cntA[e]; }
        g_seg[8] = TK;
        g_seg[9] = TKS;
        // dense y-tile table: only real tiles
        int nt = 0;
        for (int z = 0; z < 9; z++) {
            int cnt = g_seg[z + 1] - g_seg[z];
            int ny = (cnt + 127) >> 7;
            for (int y = 0; y < ny; y++) g_ytz[nt++] = (z << 16) | y;
        }
        g_nyt = nt;
        float aux = 0.f;
        const float invT = 1.0f / (float)TT;
        for (int e = 0; e < EE; e++)
            aux += ((float)g_cnt1[e] * invT) * (g_psum[e] * invT);
        aux_out[0] = 0.01f * (float)EE * aux;
    }
}

__global__ void build_kernel() {
    int t = blockIdx.x * blockDim.x + threadIdx.x;
    if (t >= TT) return;
    int2 e = g_top_e[t];
    float2 p = g_top_p[t];
    int pos0 = g_seg[e.x] + atomicAdd(&g_cur[e.x], 1);
    g_tok[pos0] = t; g_gatev[pos0] = p.x; g_pos[2 * t] = pos0;
    int pos1 = g_seg[e.y] + atomicAdd(&g_cur[e.y], 1);
    g_tok[pos1] = t; g_gatev[pos1] = p.y; g_pos[2 * t + 1] = pos1;
    g_tok[TK + t] = t; g_gatev[TK + t] = 1.0f;
}

// ---------------- fp16 convert x (token order, L2-resident) ----------------
__global__ void conv_x(const float* __restrict__ x) {
    int i = blockIdx.x * blockDim.x + threadIdx.x;
    if (i >= TT * (DD / 4)) return;
    float4 v = reinterpret_cast<const float4*>(x)[i];
    long long o = (long long)i * 2;
    reinterpret_cast<__half2*>(g_xh)[o]     = __floats2half2_rn(v.x, v.y);
    reinterpret_cast<__half2*>(g_xh)[o + 1] = __floats2half2_rn(v.z, v.w);
}

// ---------------- fp16 convert all 6 weight tensors (one launch) ----------
__global__ void conv_w_all(const float* __restrict__ w1, const float* __restrict__ sw1,
                           const float* __restrict__ w3, const float* __restrict__ sw3,
                           const float* __restrict__ w2, const float* __restrict__ sw2) {
    int job = blockIdx.y;                   // 0..5
    const float* src;
    __half* dst;
    int n4;
    const int nw = 8 * WMAT / 4, ns = WMAT / 4;
    switch (job) {
        case 0:  src = w1;  dst = g_w1h;                    n4 = nw; break;
        case 1:  src = sw1; dst = g_w1h + (size_t)8 * WMAT; n4 = ns; break;
        case 2:  src = w3;  dst = g_w3h;                    n4 = nw; break;
        case 3:  src = sw3; dst = g_w3h + (size_t)8 * WMAT; n4 = ns; break;
        case 4:  src = w2;  dst = g_w2h;                    n4 = nw; break;
        default: src = sw2; dst = g_w2h + (size_t)8 * WMAT; n4 = ns; break;
    }
    for (int i = blockIdx.x * blockDim.x + threadIdx.x; i < n4;
         i += gridDim.x * blockDim.x) {
        float4 v = reinterpret_cast<const float4*>(src)[i];
        long long o = (long long)i * 2;
        reinterpret_cast<__half2*>(dst)[o]     = __floats2half2_rn(v.x, v.y);
        reinterpret_cast<__half2*>(dst)[o + 1] = __floats2half2_rn(v.z, v.w);
    }
}

// ---------------- swiglu (fp16 in, fp16 out) ----------------
__global__ void swiglu_half(int n4) {
    int i = blockIdx.x * blockDim.x + threadIdx.x;
    if (i >= n4) return;
    const __half2* a2 = reinterpret_cast<const __half2*>(g_bufAh);
    const __half2* b2 = reinterpret_cast<const __half2*>(g_bufBh);
    long long o = (long long)i * 2;
    __half2 a0 = a2[o], a1 = a2[o + 1];
    __half2 b0 = b2[o], b1 = b2[o + 1];
    float ax = __low2float(a0), ay = __high2float(a0);
    float az = __low2float(a1), aw = __high2float(a1);
    float bx = __low2float(b0), by = __high2float(b0);
    float bz = __low2float(b1), bw = __high2float(b1);
    float hx = ax / (1.f + __expf(-ax)) * bx;
    float hy = ay / (1.f + __expf(-ay)) * by;
    float hz = az / (1.f + __expf(-az)) * bz;
    float hw = aw / (1.f + __expf(-aw)) * bw;
    reinterpret_cast<__half2*>(g_hh)[o]     = __floats2half2_rn(hx, hy);
    reinterpret_cast<__half2*>(g_hh)[o + 1] = __floats2half2_rn(hz, hw);
}

// ============================================================================
// persistent grouped FP16 GEMM via mma.sync m16n8k16 (fp32 accumulate)
// 128x128 CTA tile, K64 chunks, 3-stage pipeline, ONE sync per chunk.
// Work-stealing: CTAs pull dense tile indices (cx fastest) from a counter.
// gate == null -> fp16 output; gate != null -> gated fp32 output.
// Optional per-tile row gather for A. W3 selects merged-GEMM1 second half.
// ============================================================================
#define MPITCH 144                          // 128B K64 data + 16B stagger
#define MTILE  (128 * MPITCH)               // 18432 bytes per operand tile
#define HSTAGE (2 * MTILE)                  // 36864 (A, B)
#define HSMEM  (3 * HSTAGE)                 // 110592 bytes total

__device__ __forceinline__ void ld_tiles_h(
    unsigned tb, int tid,
    const __half* __restrict__ A, const __half* __restrict__ B,
    const int* __restrict__ stok,           // smem token map or null
    int row0, int lda, int col0, int ldb, int nreal, int kreal, int kc0)
{
#pragma unroll
    for (int j = 0; j < 8; j++) {
        int idx = j * 256 + tid;         // 0..2047
        int li = idx & 1023;
        int r = li >> 3, c = li & 7;     // tile row, 16B k-chunk (8 halves)
        unsigned off = (unsigned)(r * MPITCH + c * 16);
        if (idx < 1024) {
            int ar;
            if (stok) ar = stok[r];
            else { ar = row0 + r; if (ar >= TKS) ar = TKS - 1; }
            long long ga = (long long)ar * lda + kc0 + c * 8;
            CP16(tb + off, A + ga, 16);
        } else {
            int n = col0 + r, kg = kc0 + c * 8;
            int ok = (n < nreal && kg < kreal) ? 16 : 0;
            long long gb = ok ? ((long long)n * ldb + kg) : 0;
            CP16(tb + MTILE + off, B + gb, ok);
        }
    }
    CP_COMMIT();
}

__global__ __launch_bounds__(256, 2)
void gemm_h(const __half* __restrict__ A,
            const __half* __restrict__ W1, const __half* __restrict__ W3,
            void* __restrict__ C1, void* __restrict__ C3,
            const float* __restrict__ gate,
            const int* __restrict__ gather,
            int* __restrict__ counter,
            int lda, int ldb, int ldc, int nreal, int kreal, int kpad, int nx)
{
    extern __shared__ __align__(128) char smem[];
    __shared__ int s_tok[128];
    __shared__ int s_li;

    unsigned sb = smem_u32(smem);
    int tid = threadIdx.x, wid = tid >> 5, lane = tid & 31;
    int nch = kpad / 64;
    int wm = wid & 3, wn = wid >> 2;          // warp -> (m32 slot, n64 slot)
    int nx_total = (W3 != nullptr) ? 2 * nx : nx;

    // ldmatrix lane offsets (f16 family; k-step byte advance added in loop)
    unsigned a_off[2], b_off[4];
#pragma unroll
    for (int t = 0; t < 2; t++) {
        int rr = wm * 32 + t * 16 + ((lane >> 3) & 1) * 8 + (lane & 7);
        a_off[t] = (unsigned)(rr * MPITCH + (lane >> 4) * 16);
    }
#pragma unroll
    for (int p = 0; p < 4; p++) {
        int nn = wn * 64 + p * 16 + (lane >> 4) * 8 + (lane & 7);
        b_off[p] = (unsigned)(nn * MPITCH + ((lane >> 3) & 1) * 16);
    }

    while (true) {
        // grab next tile (broadcast through smem); sync also fences smem reuse
        if (tid == 0) s_li = atomicAdd(counter, 1);
        __syncthreads();
        int li = s_li;
        int total = g_nyt * nx_total;
        if (li >= total) break;

        int cx = li % nx_total;
        int yt = li / nx_total;
        int packed = g_ytz[yt];
        int z = packed >> 16;
        int y = packed & 0xFFFF;

        int m0 = g_seg[z], m1 = g_seg[z + 1];
        int row0 = m0 + y * 128;

        const __half* W = W1;
        void* C = C1;
        if (W3 != nullptr && cx >= nx) { W = W3; C = C3; cx -= nx; }
        int col0 = cx * 128;
        const __half* B = W + (long long)z * WMAT;

        if (gather != nullptr) {
            if (tid < 128) {
                int rr = row0 + tid;
                s_tok[tid] = gather[(rr < m1) ? rr : m0];
            }
            __syncthreads();
        }
        const int* stok = (gather != nullptr) ? s_tok : nullptr;

        float acc[2][8][4];
#pragma unroll
        for (int t = 0; t < 2; t++)
#pragma unroll
            for (int n = 0; n < 8; n++)
#pragma unroll
                for (int q = 0; q < 4; q++) acc[t][n][q] = 0.f;

        // prologue: stages 0, 1 <- chunks 0, 1
        ld_tiles_h(sb,          tid, A, B, stok, row0, lda, col0, ldb, nreal, kreal, 0);
        ld_tiles_h(sb + HSTAGE, tid, A, B, stok, row0, lda, col0, ldb, nreal, kreal, 64);

        for (int i = 0; i < nch; i++) {
            if (i + 1 < nch) CP_WAIT1(); else CP_WAIT0();
            __syncthreads();
            if (i + 2 < nch) {
                ld_tiles_h(sb + ((i + 2) % 3) * HSTAGE, tid, A, B, stok,
                           row0, lda, col0, ldb, nreal, kreal, (i + 2) * 64);
            }

            unsigned tb = sb + (i % 3) * HSTAGE;
#pragma unroll
            for (int ks = 0; ks < 4; ks++) {
                unsigned kof = ks * 32;      // 16 halves = 32 bytes per k16 step
                unsigned av[2][4], bv[4][4];
                LDSM4(av[0], tb + a_off[0] + kof);
                LDSM4(av[1], tb + a_off[1] + kof);
#pragma unroll
                for (int p = 0; p < 4; p++)
                    LDSM4(bv[p], tb + MTILE + b_off[p] + kof);
#pragma unroll
                for (int p = 0; p < 4; p++)
#pragma unroll
                    for (int t = 0; t < 2; t++) {
                        MMAF16(acc[t][2 * p],     av[t], bv[p][0], bv[p][1]);
                        MMAF16(acc[t][2 * p + 1], av[t], bv[p][2], bv[p][3]);
                    }
            }
        }

        // epilogue
#pragma unroll
        for (int t = 0; t < 2; t++) {
            int r0 = row0 + wm * 32 + t * 16 + (lane >> 2);
            int r1 = r0 + 8;
            bool a0 = (r0 < m1), a1 = (r1 < m1);
            if (gate != nullptr) {
                float g0 = a0 ? gate[r0] : 1.f;
                float g1 = a1 ? gate[r1] : 1.f;
                float* Cf = (float*)C;
#pragma unroll
                for (int n = 0; n < 8; n++) {
                    int cb = col0 + wn * 64 + n * 8 + 2 * (lane & 3);
                    if (a0) {
                        float2 v = make_float2(acc[t][n][0] * g0, acc[t][n][1] * g0);
                        *reinterpret_cast<float2*>(Cf + (long long)r0 * ldc + cb) = v;
                    }
                    if (a1) {
                        float2 v = make_float2(acc[t][n][2] * g1, acc[t][n][3] * g1);
                        *reinterpret_cast<float2*>(Cf + (long long)r1 * ldc + cb) = v;
                    }
                }
            } else {
                __half* Ch = (__half*)C;
#pragma unroll
                for (int n = 0; n < 8; n++) {
                    int cb = col0 + wn * 64 + n * 8 + 2 * (lane & 3);
                    if (a0) {
                        *reinterpret_cast<__half2*>(Ch + (long long)r0 * ldc + cb) =
                            __floats2half2_rn(acc[t][n][0], acc[t][n][1]);
                    }
                    if (a1) {
                        *reinterpret_cast<__half2*>(Ch + (long long)r1 * ldc + cb) =
                            __floats2half2_rn(acc[t][n][2], acc[t][n][3]);
                    }
                }
            }
        }
    }
}

// ---------------- final deterministic 3-slot add ----------------
__global__ void final_add(float* __restrict__ out) {
    int i = blockIdx.x * blockDim.x + threadIdx.x;
    if (i >= TT * (DD / 4)) return;
    int t = i >> 9, c = i & 511;
    int p0 = g_pos[2 * t], p1 = g_pos[2 * t + 1], p2 = TK + t;
    const float4* y4 = reinterpret_cast<const float4*>(g_y);
    float4 a = y4[(long long)p0 * 512 + c];
    float4 b = y4[(long long)p1 * 512 + c];
    float4 d = y4[(long long)p2 * 512 + c];
    float4 v;
    v.x = a.x + b.x + d.x; v.y = a.y + b.y + d.y;
    v.z = a.z + b.z + d.z; v.w = a.w + b.w + d.w;
    reinterpret_cast<float4*>(out)[(long long)t * 512 + c] = v;
}

// ---------------- launch ----------------
extern "C" void kernel_launch(void* const* d_in, const int* in_sizes, int n_in,
                              void* d_out, int out_size) {
    const float* x   = (const float*)d_in[0];
    const float* rw  = (const float*)d_in[1];
    const float* w1  = (const float*)d_in[2];
    const float* w2  = (const float*)d_in[3];
    const float* w3  = (const float*)d_in[4];
    const float* sw1 = (const float*)d_in[5];
    const float* sw2 = (const float*)d_in[6];
    const float* sw3 = (const float*)d_in[7];
    float* out = (float*)d_out;

    float *pY, *pGate;
    __half *pXh, *pHh, *pBufAh, *pBufBh, *pW1h, *pW3h, *pW2h;
    int *pTok, *pW1c, *pW2c;
    cudaGetSymbolAddress((void**)&pY,     g_y);
    cudaGetSymbolAddress((void**)&pGate,  g_gatev);
    cudaGetSymbolAddress((void**)&pXh,    g_xh);
    cudaGetSymbolAddress((void**)&pHh,    g_hh);
    cudaGetSymbolAddress((void**)&pBufAh, g_bufAh);
    cudaGetSymbolAddress((void**)&pBufBh, g_bufBh);
    cudaGetSymbolAddress((void**)&pW1h,   g_w1h);
    cudaGetSymbolAddress((void**)&pW3h,   g_w3h);
    cudaGetSymbolAddress((void**)&pW2h,   g_w2h);
    cudaGetSymbolAddress((void**)&pTok,   g_tok);
    cudaGetSymbolAddress((void**)&pW1c,   g_work1);
    cudaGetSymbolAddress((void**)&pW2c,   g_work2);

    cudaFuncSetAttribute(gemm_h, cudaFuncAttributeMaxDynamicSharedMemorySize, HSMEM);

    // routing
    init_kernel<<<1, 32>>>();
    router_kernel<<<TT / 8, 256>>>(x, rw);
    scan_kernel<<<1, 32>>>(out + (long long)TT * DD);
    build_kernel<<<TT / 256, 256>>>();

    // converts (x token order; all 6 weight tensors in one launch)
    conv_x<<<(TT * (DD / 4) + 255) / 256, 256>>>(x);
    {
        dim3 gw(1184, 6);
        conv_w_all<<<gw, 256>>>(w1, sw1, w3, sw3, w2, sw2);
    }

    // GEMM1 merged + in-GEMM gather (work-stealing persistent CTAs)
    gemm_h<<<NPERS, 256, HSMEM>>>(pXh, pW1h, pW3h, pBufAh, pBufBh, nullptr, pTok,
                                  pW1c, DD, DD, HP, HH, DD, 2048, 11);

    // swiglu (fp16 -> fp16)
    {
        int n4 = TKS * HP / 4;
        swiglu_half<<<(n4 + 255) / 256, 256>>>(n4);
    }

    // GEMM2: [TKS, HP] @ [DD, HH]^T -> y (gated fp32); kpad 1408
    gemm_h<<<NPERS, 256, HSMEM>>>(pHh, pW2h, nullptr, pY, nullptr, pGate, nullptr,
                                  pW2c, HP, HH, DD, DD, HH, 1408, 16);

    final_add<<<(TT * (DD / 4)) / 256, 256>>>(out);
}

// round 17
// speedup vs baseline: 1.1351x; 1.0252x over previous
#include <cuda_runtime.h>
#include <cuda_fp16.h>
#include <math.h>
#include <stdint.h>

// ---------------- problem constants ----------------
#define TT   8192              // tokens (B*S)
#define DD   2048              // model dim
#define HH   1368              // hidden dim
#define HP   1408              // hidden padded to 64
#define EE   8                 // experts
#define TK   16384             // T * K routed assignments
#define TKS  24576             // TK + TT (shared expert appended as segment 8)
#define WMAT (HH * DD)         // elements per weight matrix

// ---------------- static device scratch ----------------
__device__ __align__(16) __half g_xh[(size_t)TT * DD];      // x (fp16, token order)
__device__ __align__(16) __half g_hh[(size_t)TKS * HP];     // swiglu output (fp16)
__device__ __align__(16) __half g_bufAh[(size_t)TKS * HP];  // x@w1^T (fp16)
__device__ __align__(16) __half g_bufBh[(size_t)TKS * HP];  // x@w3^T (fp16)
__device__ __align__(16) __half g_yh[(size_t)TKS * DD];     // gemm2 slots (fp16)
__device__ __align__(16) __half g_w1h[(size_t)9 * WMAT];
__device__ __align__(16) __half g_w3h[(size_t)9 * WMAT];
__device__ __align__(16) __half g_w2h[(size_t)9 * WMAT];
__device__ int    g_tok[TKS];
__device__ float  g_gatev[TKS];
__device__ int    g_pos[2 * TT];
__device__ int2   g_top_e[TT];
__device__ float2 g_top_p[TT];
__device__ int    g_cnt1[EE];
__device__ int    g_cntA[EE];
__device__ int    g_cur[EE];
__device__ int    g_seg[10];
__device__ float  g_psum[EE];

// ---------------- PTX helpers (baseline-arch safe) ----------------
__device__ __forceinline__ unsigned smem_u32(const void* p) {
    unsigned a;
    asm("{ .reg .u64 t; cvta.to.shared.u64 t, %1; cvt.u32.u64 %0, t; }"
        : "=r"(a) : "l"(p));
    return a;
}
#define CP_COMMIT()  asm volatile("cp.async.commit_group;" ::: "memory")
#define CP_WAIT0()   asm volatile("cp.async.wait_group 0;" ::: "memory")
#define CP_WAIT1()   asm volatile("cp.async.wait_group 1;" ::: "memory")
#define CP16(dst, src, sz) \
    asm volatile("cp.async.cg.shared.global [%0], [%1], 16, %2;" \
                 :: "r"(dst), "l"(src), "r"(sz))

#define LDSM4(r, addr) \
    asm volatile("ldmatrix.sync.aligned.m8n8.x4.shared.b16 {%0,%1,%2,%3}, [%4];" \
        : "=r"((r)[0]), "=r"((r)[1]), "=r"((r)[2]), "=r"((r)[3]) : "r"(addr))

#define MMAF16(c, a, b0, b1) \
    asm volatile("mma.sync.aligned.m16n8k16.row.col.f32.f16.f16.f32 " \
        "{%0,%1,%2,%3}, {%4,%5,%6,%7}, {%8,%9}, {%0,%1,%2,%3};" \
        : "+f"((c)[0]), "+f"((c)[1]), "+f"((c)[2]), "+f"((c)[3]) \
        : "r"((a)[0]), "r"((a)[1]), "r"((a)[2]), "r"((a)[3]), "r"(b0), "r"(b1))

// ---------------- routing ----------------
__global__ void init_kernel() {
    int i = threadIdx.x;
    if (i < EE) { g_cnt1[i] = 0; g_cntA[i] = 0; g_psum[i] = 0.f; g_cur[i] = 0; }
}

__global__ void router_kernel(const float* __restrict__ x,
                              const float* __restrict__ rw) {
    __shared__ float s_psum[EE];
    __shared__ int s_cnt1[EE], s_cntA[EE];
    int tid = threadIdx.x;
    if (tid < EE) { s_psum[tid] = 0.f; s_cnt1[tid] = 0; s_cntA[tid] = 0; }
    __syncthreads();

    int warp = tid >> 5, lane = tid & 31;
    int t = blockIdx.x * 8 + warp;

    float acc[EE];
#pragma unroll
    for (int e = 0; e < EE; e++) acc[e] = 0.f;
    const float4* xr = reinterpret_cast<const float4*>(x + (long long)t * DD);
    for (int d4 = lane; d4 < DD / 4; d4 += 32) {
        float4 xv = xr[d4];
#pragma unroll
        for (int e = 0; e < EE; e++) {
            float4 wv = reinterpret_cast<const float4*>(rw + (long long)e * DD)[d4];
            acc[e] += xv.x * wv.x + xv.y * wv.y + xv.z * wv.z + xv.w * wv.w;
        }
    }
#pragma unroll
    for (int e = 0; e < EE; e++)
        for (int o = 16; o; o >>= 1)
            acc[e] += __shfl_xor_sync(0xffffffffu, acc[e], o);

    if (lane == 0) {
        float mx = acc[0];
#pragma unroll
        for (int e = 1; e < EE; e++) mx = fmaxf(mx, acc[e]);
        float p[EE], s = 0.f;
#pragma unroll
        for (int e = 0; e < EE; e++) { p[e] = expf(acc[e] - mx); s += p[e]; }
        float inv = 1.f / s;
        int e0 = 0;
#pragma unroll
        for (int e = 1; e < EE; e++) if (acc[e] > acc[e0]) e0 = e;
        int e1 = (e0 == 0) ? 1 : 0;
#pragma unroll
        for (int e = 0; e < EE; e++) if (e != e0 && acc[e] > acc[e1]) e1 = e;

        g_top_e[t] = make_int2(e0, e1);
        g_top_p[t] = make_float2(p[e0] * inv, p[e1] * inv);
        atomicAdd(&s_cnt1[e0], 1);
        atomicAdd(&s_cntA[e0], 1);
        atomicAdd(&s_cntA[e1], 1);
#pragma unroll
        for (int e = 0; e < EE; e++) atomicAdd(&s_psum[e], p[e] * inv);
    }
    __syncthreads();
    if (tid < EE) {
        atomicAdd(&g_psum[tid], s_psum[tid]);
        atomicAdd(&g_cnt1[tid], s_cnt1[tid]);
        atomicAdd(&g_cntA[tid], s_cntA[tid]);
    }
}

__global__ void scan_kernel(float* __restrict__ aux_out) {
    if (threadIdx.x == 0) {
        int off = 0;
        for (int e = 0; e < EE; e++) { g_seg[e] = off; off += g_cntA[e]; }
        g_seg[8] = TK;
        g_seg[9] = TKS;
        float aux = 0.f;
        const float invT = 1.0f / (float)TT;
        for (int e = 0; e < EE; e++)
            aux += ((float)g_cnt1[e] * invT) * (g_psum[e] * invT);
        aux_out[0] = 0.01f * (float)EE * aux;
    }
}

__global__ void build_kernel() {
    int t = blockIdx.x * blockDim.x + threadIdx.x;
    if (t >= TT) return;
    int2 e = g_top_e[t];
    float2 p = g_top_p[t];
    int pos0 = g_seg[e.x] + atomicAdd(&g_cur[e.x], 1);
    g_tok[pos0] = t; g_gatev[pos0] = p.x; g_pos[2 * t] = pos0;
    int pos1 = g_seg[e.y] + atomicAdd(&g_cur[e.y], 1);
    g_tok[pos1] = t; g_gatev[pos1] = p.y; g_pos[2 * t + 1] = pos1;
    g_tok[TK + t] = t; g_gatev[TK + t] = 1.0f;
}

// ---------------- fp16 convert x (token order, L2-resident) ----------------
__global__ void conv_x(const float* __restrict__ x) {
    int i = blockIdx.x * blockDim.x + threadIdx.x;
    if (i >= TT * (DD / 4)) return;
    float4 v = reinterpret_cast<const float4*>(x)[i];
    long long o = (long long)i * 2;
    reinterpret_cast<__half2*>(g_xh)[o]     = __floats2half2_rn(v.x, v.y);
    reinterpret_cast<__half2*>(g_xh)[o + 1] = __floats2half2_rn(v.z, v.w);
}

// ---------------- fp16 convert all 6 weight tensors (one launch) ----------
__global__ void conv_w_all(const float* __restrict__ w1, const float* __restrict__ sw1,
                           const float* __restrict__ w3, const float* __restrict__ sw3,
                           const float* __restrict__ w2, const float* __restrict__ sw2) {
    int job = blockIdx.y;                   // 0..5
    const float* src;
    __half* dst;
    int n4;
    const int nw = 8 * WMAT / 4, ns = WMAT / 4;
    switch (job) {
        case 0:  src = w1;  dst = g_w1h;                    n4 = nw; break;
        case 1:  src = sw1; dst = g_w1h + (size_t)8 * WMAT; n4 = ns; break;
        case 2:  src = w3;  dst = g_w3h;                    n4 = nw; break;
        case 3:  src = sw3; dst = g_w3h + (size_t)8 * WMAT; n4 = ns; break;
        case 4:  src = w2;  dst = g_w2h;                    n4 = nw; break;
        default: src = sw2; dst = g_w2h + (size_t)8 * WMAT; n4 = ns; break;
    }
    for (int i = blockIdx.x * blockDim.x + threadIdx.x; i < n4;
         i += gridDim.x * blockDim.x) {
        float4 v = reinterpret_cast<const float4*>(src)[i];
        long long o = (long long)i * 2;
        reinterpret_cast<__half2*>(dst)[o]     = __floats2half2_rn(v.x, v.y);
        reinterpret_cast<__half2*>(dst)[o + 1] = __floats2half2_rn(v.z, v.w);
    }
}

// ---------------- swiglu (fp16 in, fp16 out) ----------------
__global__ void swiglu_half(int n4) {
    int i = blockIdx.x * blockDim.x + threadIdx.x;
    if (i >= n4) return;
    const __half2* a2 = reinterpret_cast<const __half2*>(g_bufAh);
    const __half2* b2 = reinterpret_cast<const __half2*>(g_bufBh);
    long long o = (long long)i * 2;
    __half2 a0 = a2[o], a1 = a2[o + 1];
    __half2 b0 = b2[o], b1 = b2[o + 1];
    float ax = __low2float(a0), ay = __high2float(a0);
    float az = __low2float(a1), aw = __high2float(a1);
    float bx = __low2float(b0), by = __high2float(b0);
    float bz = __low2float(b1), bw = __high2float(b1);
    float hx = ax / (1.f + __expf(-ax)) * bx;
    float hy = ay / (1.f + __expf(-ay)) * by;
    float hz = az / (1.f + __expf(-az)) * bz;
    float hw = aw / (1.f + __expf(-aw)) * bw;
    reinterpret_cast<__half2*>(g_hh)[o]     = __floats2half2_rn(hx, hy);
    reinterpret_cast<__half2*>(g_hh)[o + 1] = __floats2half2_rn(hz, hw);
}

// ============================================================================
// grouped FP16 GEMM via mma.sync m16n8k16 (fp32 accumulate)
// C[m, col] = sum_k A[g(m),k] * W[z][n,k]
// 128x128 CTA tile, K64 chunks, 3-stage pipeline, ONE sync per chunk.
// gate == null -> fp16 output (GEMM1); gate != null -> gated FP16 output
// (GEMM2: gate multiply in fp32, then rn-round to fp16 slots).
// Optional per-tile row gather for A. W3 selects merged-GEMM1 second half.
// ============================================================================
#define MPITCH 144                          // 128B K64 data + 16B stagger
#define MTILE  (128 * MPITCH)               // 18432 bytes per operand tile
#define HSTAGE (2 * MTILE)                  // 36864 (A, B)
#define HSMEM  (3 * HSTAGE)                 // 110592 bytes total

__device__ __forceinline__ void ld_tiles_h(
    unsigned tb, int tid,
    const __half* __restrict__ A, const __half* __restrict__ B,
    const int* __restrict__ stok,           // smem token map or null
    int row0, int lda, int col0, int ldb, int nreal, int kreal, int kc0)
{
#pragma unroll
    for (int j = 0; j < 8; j++) {
        int idx = j * 256 + tid;         // 0..2047
        int li = idx & 1023;
        int r = li >> 3, c = li & 7;     // tile row, 16B k-chunk (8 halves)
        unsigned off = (unsigned)(r * MPITCH + c * 16);
        if (idx < 1024) {
            int ar;
            if (stok) ar = stok[r];
            else { ar = row0 + r; if (ar >= TKS) ar = TKS - 1; }
            long long ga = (long long)ar * lda + kc0 + c * 8;
            CP16(tb + off, A + ga, 16);
        } else {
            int n = col0 + r, kg = kc0 + c * 8;
            int ok = (n < nreal && kg < kreal) ? 16 : 0;
            long long gb = ok ? ((long long)n * ldb + kg) : 0;
            CP16(tb + MTILE + off, B + gb, ok);
        }
    }
    CP_COMMIT();
}

__global__ __launch_bounds__(256, 2)
void gemm_h(const __half* __restrict__ A,
            const __half* __restrict__ W1, const __half* __restrict__ W3,
            __half* __restrict__ C1, __half* __restrict__ C3,
            const float* __restrict__ gate,
            const int* __restrict__ gather,
            int lda, int ldb, int ldc, int nreal, int kreal, int kpad, int nx)
{
    extern __shared__ __align__(128) char smem[];
    __shared__ int s_tok[128];

    int z  = blockIdx.z;
    int m0 = g_seg[z], m1 = g_seg[z + 1];
    int row0 = m0 + blockIdx.y * 128;
    if (row0 >= m1) return;

    const __half* W = W1;
    __half* C = C1;
    int cx = blockIdx.x;
    if (W3 != nullptr && cx >= nx) { W = W3; C = C3; cx -= nx; }
    int col0 = cx * 128;
    const __half* B = W + (long long)z * WMAT;

    unsigned sb = smem_u32(smem);
    int tid = threadIdx.x, wid = tid >> 5, lane = tid & 31;
    int nch = kpad / 64;
    int wm = wid & 3, wn = wid >> 2;          // warp -> (m32 slot, n64 slot)

    // stage token map for gathered A rows
    if (gather != nullptr) {
        if (tid < 128) {
            int rr = row0 + tid;
            s_tok[tid] = gather[(rr < m1) ? rr : m0];
        }
        __syncthreads();
    }
    const int* stok = (gather != nullptr) ? s_tok : nullptr;

    float acc[2][8][4];
#pragma unroll
    for (int t = 0; t < 2; t++)
#pragma unroll
        for (int n = 0; n < 8; n++)
#pragma unroll
            for (int q = 0; q < 4; q++) acc[t][n][q] = 0.f;

    // ldmatrix lane offsets (f16 family; k-step byte advance added in loop)
    unsigned a_off[2], b_off[4];
#pragma unroll
    for (int t = 0; t < 2; t++) {
        int rr = wm * 32 + t * 16 + ((lane >> 3) & 1) * 8 + (lane & 7);
        a_off[t] = (unsigned)(rr * MPITCH + (lane >> 4) * 16);
    }
#pragma unroll
    for (int p = 0; p < 4; p++) {
        int nn = wn * 64 + p * 16 + (lane >> 4) * 8 + (lane & 7);
        b_off[p] = (unsigned)(nn * MPITCH + ((lane >> 3) & 1) * 16);
    }

    // prologue: stages 0, 1 <- chunks 0, 1
    ld_tiles_h(sb,          tid, A, B, stok, row0, lda, col0, ldb, nreal, kreal, 0);
    ld_tiles_h(sb + HSTAGE, tid, A, B, stok, row0, lda, col0, ldb, nreal, kreal, 64);

    for (int i = 0; i < nch; i++) {
        if (i + 1 < nch) CP_WAIT1(); else CP_WAIT0();
        __syncthreads();
        if (i + 2 < nch) {
            ld_tiles_h(sb + ((i + 2) % 3) * HSTAGE, tid, A, B, stok,
                       row0, lda, col0, ldb, nreal, kreal, (i + 2) * 64);
        }

        unsigned tb = sb + (i % 3) * HSTAGE;
#pragma unroll
        for (int ks = 0; ks < 4; ks++) {
            unsigned kof = ks * 32;          // 16 halves = 32 bytes per k16 step
            unsigned av[2][4], bv[4][4];
            LDSM4(av[0], tb + a_off[0] + kof);
            LDSM4(av[1], tb + a_off[1] + kof);
#pragma unroll
            for (int p = 0; p < 4; p++)
                LDSM4(bv[p], tb + MTILE + b_off[p] + kof);
#pragma unroll
            for (int p = 0; p < 4; p++)
#pragma unroll
                for (int t = 0; t < 2; t++) {
                    MMAF16(acc[t][2 * p],     av[t], bv[p][0], bv[p][1]);
                    MMAF16(acc[t][2 * p + 1], av[t], bv[p][2], bv[p][3]);
                }
        }
    }

    // epilogue: fp16 output; gate multiply (fp32) when gate != null
#pragma unroll
    for (int t = 0; t < 2; t++) {
        int r0 = row0 + wm * 32 + t * 16 + (lane >> 2);
        int r1 = r0 + 8;
        bool a0 = (r0 < m1), a1 = (r1 < m1);
        float g0 = 1.f, g1 = 1.f;
        if (gate != nullptr) {
            if (a0) g0 = gate[r0];
            if (a1) g1 = gate[r1];
        }
#pragma unroll
        for (int n = 0; n < 8; n++) {
            int cb = col0 + wn * 64 + n * 8 + 2 * (lane & 3);
            if (a0) {
                *reinterpret_cast<__half2*>(C + (long long)r0 * ldc + cb) =
                    __floats2half2_rn(acc[t][n][0] * g0, acc[t][n][1] * g0);
            }
            if (a1) {
                *reinterpret_cast<__half2*>(C + (long long)r1 * ldc + cb) =
                    __floats2half2_rn(acc[t][n][2] * g1, acc[t][n][3] * g1);
            }
        }
    }
}

// ---------------- final deterministic 3-slot add (fp16 slots -> fp32 out) --
__global__ void final_add(float* __restrict__ out) {
    int i = blockIdx.x * blockDim.x + threadIdx.x;
    if (i >= TT * (DD / 4)) return;
    int t = i >> 9, c = i & 511;                  // c indexes groups of 4
    int p0 = g_pos[2 * t], p1 = g_pos[2 * t + 1], p2 = TK + t;
    const __half2* y2 = reinterpret_cast<const __half2*>(g_yh);
    long long o0 = (long long)p0 * (DD / 2) + c * 2;
    long long o1 = (long long)p1 * (DD / 2) + c * 2;
    long long o2 = (long long)p2 * (DD / 2) + c * 2;
    __half2 a0 = y2[o0], a1 = y2[o0 + 1];
    __half2 b0 = y2[o1], b1 = y2[o1 + 1];
    __half2 d0 = y2[o2], d1 = y2[o2 + 1];
    float4 v;
    v.x = __low2float(a0)  + __low2float(b0)  + __low2float(d0);
    v.y = __high2float(a0) + __high2float(b0) + __high2float(d0);
    v.z = __low2float(a1)  + __low2float(b1)  + __low2float(d1);
    v.w = __high2float(a1) + __high2float(b1) + __high2float(d1);
    reinterpret_cast<float4*>(out)[(long long)t * 512 + c] = v;
}

// ---------------- launch ----------------
extern "C" void kernel_launch(void* const* d_in, const int* in_sizes, int n_in,
                              void* d_out, int out_size) {
    const float* x   = (const float*)d_in[0];
    const float* rw  = (const float*)d_in[1];
    const float* w1  = (const float*)d_in[2];
    const float* w2  = (const float*)d_in[3];
    const float* w3  = (const float*)d_in[4];
    const float* sw1 = (const float*)d_in[5];
    const float* sw2 = (const float*)d_in[6];
    const float* sw3 = (const float*)d_in[7];
    float* out = (float*)d_out;

    float *pGate;
    __half *pXh, *pHh, *pBufAh, *pBufBh, *pYh, *pW1h, *pW3h, *pW2h;
    int *pTok;
    cudaGetSymbolAddress((void**)&pGate,  g_gatev);
    cudaGetSymbolAddress((void**)&pXh,    g_xh);
    cudaGetSymbolAddress((void**)&pHh,    g_hh);
    cudaGetSymbolAddress((void**)&pBufAh, g_bufAh);
    cudaGetSymbolAddress((void**)&pBufBh, g_bufBh);
    cudaGetSymbolAddress((void**)&pYh,    g_yh);
    cudaGetSymbolAddress((void**)&pW1h,   g_w1h);
    cudaGetSymbolAddress((void**)&pW3h,   g_w3h);
    cudaGetSymbolAddress((void**)&pW2h,   g_w2h);
    cudaGetSymbolAddress((void**)&pTok,   g_tok);

    cudaFuncSetAttribute(gemm_h, cudaFuncAttributeMaxDynamicSharedMemorySize, HSMEM);

    // routing
    init_kernel<<<1, 32>>>();
    router_kernel<<<TT / 8, 256>>>(x, rw);
    scan_kernel<<<1, 32>>>(out + (long long)TT * DD);
    build_kernel<<<TT / 256, 256>>>();

    // converts (x token order; all 6 weight tensors in one launch)
    conv_x<<<(TT * (DD / 4) + 255) / 256, 256>>>(x);
    {
        dim3 gw(1184, 6);
        conv_w_all<<<gw, 256>>>(w1, sw1, w3, sw3, w2, sw2);
    }

    // GEMM1 merged + in-GEMM gather: x<11 -> w1 -> bufA; >=11 -> w3 -> bufB
    dim3 grid1(22, 64, 9);
    gemm_h<<<grid1, 256, HSMEM>>>(pXh, pW1h, pW3h, pBufAh, pBufBh, nullptr, pTok,
                                  DD, DD, HP, HH, DD, 2048, 11);

    // swiglu (fp16 -> fp16)
    {
        int n4 = TKS * HP / 4;
        swiglu_half<<<(n4 + 255) / 256, 256>>>(n4);
    }

    // GEMM2: [TKS, HP] @ [DD, HH]^T -> y slots (gated, fp16); kpad 1408
    dim3 grid2(16, 64, 9);
    gemm_h<<<grid2, 256, HSMEM>>>(pHh, pW2h, nullptr, pYh, nullptr, pGate, nullptr,
                                  HP, HH, DD, DD, HH, 1408, 16);

    final_add<<<(TT * (DD / 4)) / 256, 256>>>(out);
}